// round 6
// baseline (speedup 1.0000x reference)
#include <cuda_runtime.h>
#include <math.h>

#define N_NODES 10000
#define C_IN 128
#define D_OUT 20
#define KNN_K 16
#define FULLM 0xffffffffu

#define KNN_TPB 256                // threads per knn block
#define WARPS_PB (KNN_TPB / 32)    // 8 warps
#define QPW 4                      // queries per warp (register-blocked)
#define QPB (WARPS_PB * QPW)       // 32 queries per block
#define TC 512                     // candidate tile
#define EPAD 22                    // emb smem row stride -> conflict-free float2

// ---------------- scratch (static device globals; no allocs) ----------------
__device__ float g_h[N_NODES * D_OUT];
__device__ float g_emb[N_NODES * D_OUT];
__device__ float g_embn[N_NODES * D_OUT];
__device__ float g_sqe[N_NODES];
__device__ float4 g_pos4[N_NODES];         // {x, y, z, sq}
__device__ float g_mu[D_OUT];
__device__ float g_rinv[D_OUT];
__device__ int   g_idx_emb[N_NODES * KNN_K];
__device__ int   g_idx_pos[N_NODES * KNN_K];

__device__ __forceinline__ float inf_f() { return __int_as_float(0x7f800000); }

// ---------------- 1) linear: h = x @ W + b ----------------
__global__ void k_linear(const float* __restrict__ x, const float* __restrict__ W,
                         const float* __restrict__ b) {
    int t = blockIdx.x * blockDim.x + threadIdx.x;
    if (t >= N_NODES * D_OUT) return;
    int i = t / D_OUT;
    int d = t % D_OUT;
    const float* xr = x + (size_t)i * C_IN;
    float acc = 0.f;
#pragma unroll 8
    for (int c = 0; c < C_IN; ++c) acc = fmaf(xr[c], W[c * D_OUT + d], acc);
    g_h[t] = acc + b[d];
}

// ---------------- 2) batchnorm stats (deterministic) ----------------
__global__ void k_stats() {
    __shared__ float ss[256];
    __shared__ float sq[256];
    int d = blockIdx.x;
    int tid = threadIdx.x;
    float s = 0.f, q = 0.f;
    for (int i = tid; i < N_NODES; i += 256) {
        float v = g_h[i * D_OUT + d];
        s += v;
        q = fmaf(v, v, q);
    }
    ss[tid] = s; sq[tid] = q;
    __syncthreads();
    for (int o = 128; o > 0; o >>= 1) {
        if (tid < o) { ss[tid] += ss[tid + o]; sq[tid] += sq[tid + o]; }
        __syncthreads();
    }
    if (tid == 0) {
        float mu = ss[0] / (float)N_NODES;
        float var = sq[0] / (float)N_NODES - mu * mu;
        g_mu[d] = mu;
        g_rinv[d] = 1.f / sqrtf(var + 1e-5f);
    }
}

// ---------------- 3) emb = relu(bn(h)); embn = emb + noise*1e-4 ----------------
__global__ void k_emb(const float* __restrict__ noise, const float* __restrict__ gamma,
                      const float* __restrict__ beta) {
    int t = blockIdx.x * blockDim.x + threadIdx.x;
    if (t >= N_NODES * D_OUT) return;
    int d = t % D_OUT;
    float e = (g_h[t] - g_mu[d]) * g_rinv[d] * gamma[d] + beta[d];
    e = fmaxf(e, 0.f);
    g_emb[t] = e;
    g_embn[t] = e + noise[t] * 1e-4f;
}

// ---------------- 4) row squared norms; build padded pos4 ----------------
// pos squared-norm mimics jnp.sum(pos*pos, axis=1): separately-rounded squares,
// left-to-right reduction, NO fma contraction (bit-match with reference).
__global__ void k_sqn(const float* __restrict__ pos) {
    int i = blockIdx.x * blockDim.x + threadIdx.x;
    if (i >= N_NODES) return;
    float s = 0.f;
#pragma unroll
    for (int d = 0; d < D_OUT; ++d) {
        float v = g_emb[i * D_OUT + d];
        s = fmaf(v, v, s);
    }
    g_sqe[i] = s;
    float p0 = pos[i * 3 + 0], p1 = pos[i * 3 + 1], p2 = pos[i * 3 + 2];
    float s0 = __fmul_rn(p0, p0);
    float s1 = __fmul_rn(p1, p1);
    float s2 = __fmul_rn(p2, p2);
    float psq = __fadd_rn(__fadd_rn(s0, s1), s2);
    g_pos4[i] = make_float4(p0, p1, p2, psq);
}

// ---------------- warp-distributed top-k ----------------
// lane r holds the r-th smallest (d2, idx); lanes >=16 overflow. All control
// flow warp-uniform. Exactness: main loop pre-filters with d2 <= kth_d
// (conservative superset); the per-hit recheck below uses the exact
// (d2, idx) lexicographic order, so selection is insert-order independent.
__device__ __forceinline__ bool lt_pair(float d2a, int ia, float d2b, int ib) {
    return (d2a < d2b) || (d2a == d2b && ia < ib);
}

// Processes all flagged lanes; returns updated kth distance (lane-15 d2).
__device__ __forceinline__ float warp_hits(unsigned mask, float d2, int jj, int lane,
                                           float& kd, int& ki) {
    float kth_d = __shfl_sync(FULLM, kd, 15);
    int   kth_i = __shfl_sync(FULLM, ki, 15);
    while (mask) {
        int src = __ffs(mask) - 1;
        mask &= mask - 1;
        float dn = __shfl_sync(FULLM, d2, src);
        int   in = __shfl_sync(FULLM, jj, src);
        if (lt_pair(dn, in, kth_d, kth_i)) {
            bool p = lt_pair(dn, in, kd, ki);
            unsigned pm = __ballot_sync(FULLM, p);
            int pos = __ffs(pm) - 1;
            float kdu = __shfl_up_sync(FULLM, kd, 1);
            int   kiu = __shfl_up_sync(FULLM, ki, 1);
            if (p) {
                kd = (lane == pos) ? dn : kdu;
                ki = (lane == pos) ? in : kiu;
            }
            kth_d = __shfl_sync(FULLM, kd, 15);
            kth_i = __shfl_sync(FULLM, ki, 15);
        }
    }
    return kth_d;
}

// ---------------- 5a) emb knn: warp handles QPW queries ----------------
__global__ void __launch_bounds__(KNN_TPB) k_knn_emb(const float* __restrict__ feat,
                                                     const float* __restrict__ sqn,
                                                     int* __restrict__ out_idx) {
    __shared__ float s_feat[TC * EPAD];
    __shared__ float s_sq[TC];
    const int lane = threadIdx.x & 31;
    const int wid = threadIdx.x >> 5;
    const int qbase = blockIdx.x * QPB + wid * QPW;

    float qv[QPW][D_OUT];
    float qsq[QPW];
    int   qid[QPW];
    bool  qok[QPW];
#pragma unroll
    for (int iq = 0; iq < QPW; ++iq) {
        int q = qbase + iq;
        qok[iq] = (q < N_NODES);
        int qc = qok[iq] ? q : 0;
        qid[iq] = q;
        qsq[iq] = sqn[qc];
#pragma unroll
        for (int d = 0; d < D_OUT; ++d) qv[iq][d] = feat[(size_t)qc * D_OUT + d];
    }

    float kd[QPW]; int ki[QPW]; float kth[QPW];
#pragma unroll
    for (int iq = 0; iq < QPW; ++iq) { kd[iq] = inf_f(); ki[iq] = 0x7fffffff; kth[iq] = inf_f(); }

    for (int base = 0; base < N_NODES; base += TC) {
        const int cnt = min(TC, N_NODES - base);
        __syncthreads();
        for (int idx = threadIdx.x; idx < cnt * D_OUT; idx += KNN_TPB) {
            int c = idx / D_OUT, d = idx - c * D_OUT;
            s_feat[c * EPAD + d] = feat[(size_t)(base + c) * D_OUT + d];
        }
        for (int idx = threadIdx.x; idx < cnt; idx += KNN_TPB)
            s_sq[idx] = sqn[base + idx];
        __syncthreads();

        for (int c0 = 0; c0 < cnt; c0 += 32) {
            const int ca = c0 + lane;
            const bool bad = (ca >= cnt);
            const int cs = bad ? 0 : ca;
            const int j = base + cs;
            const float ssq = s_sq[cs];
            const float2* ra = (const float2*)&s_feat[cs * EPAD];

            float a[QPW];
#pragma unroll
            for (int iq = 0; iq < QPW; ++iq) a[iq] = 0.f;
#pragma unroll
            for (int kk = 0; kk < D_OUT / 2; ++kk) {
                float2 v = ra[kk];
#pragma unroll
                for (int iq = 0; iq < QPW; ++iq) {
                    a[iq] = fmaf(qv[iq][2 * kk], v.x, a[iq]);
                    a[iq] = fmaf(qv[iq][2 * kk + 1], v.y, a[iq]);
                }
            }
#pragma unroll
            for (int iq = 0; iq < QPW; ++iq) {
                float d2 = fmaf(-2.f, a[iq], qsq[iq] + ssq);
                int jj = j;
                if (bad || j == qid[iq] || !qok[iq]) { d2 = inf_f(); jj = 0x7fffffff; }
                unsigned m = __ballot_sync(FULLM, d2 <= kth[iq]);
                if (m) kth[iq] = warp_hits(m, d2, jj, lane, kd[iq], ki[iq]);
            }
        }
    }
#pragma unroll
    for (int iq = 0; iq < QPW; ++iq)
        if (qok[iq] && lane < KNN_K) out_idx[qid[iq] * KNN_K + lane] = ki[iq];
}

// ---------------- 5b) pos knn: warp handles QPW queries ----------------
__global__ void __launch_bounds__(KNN_TPB) k_knn_pos(const float4* __restrict__ p4,
                                                     int* __restrict__ out_idx) {
    __shared__ float4 s_p[TC];
    const int lane = threadIdx.x & 31;
    const int wid = threadIdx.x >> 5;
    const int qbase = blockIdx.x * QPB + wid * QPW;

    float4 qp[QPW];
    int qid[QPW];
    bool qok[QPW];
#pragma unroll
    for (int iq = 0; iq < QPW; ++iq) {
        int q = qbase + iq;
        qok[iq] = (q < N_NODES);
        qid[iq] = q;
        qp[iq] = p4[qok[iq] ? q : 0];
    }

    float kd[QPW]; int ki[QPW]; float kth[QPW];
#pragma unroll
    for (int iq = 0; iq < QPW; ++iq) { kd[iq] = inf_f(); ki[iq] = 0x7fffffff; kth[iq] = inf_f(); }

    for (int base = 0; base < N_NODES; base += TC) {
        const int cnt = min(TC, N_NODES - base);
        __syncthreads();
        for (int idx = threadIdx.x; idx < cnt; idx += KNN_TPB)
            s_p[idx] = p4[base + idx];
        __syncthreads();

        for (int c0 = 0; c0 < cnt; c0 += 32) {
            const int ca = c0 + lane;
            const bool bad = (ca >= cnt);
            const int cs = bad ? 0 : ca;
            const int j = base + cs;
            const float4 v = s_p[cs];
#pragma unroll
            for (int iq = 0; iq < QPW; ++iq) {
                // dot as ascending fma chain; d2 = fl(fl(sqi+sqj) - fl(2*dot))
                float a = fmaf(qp[iq].x, v.x, 0.f);
                a = fmaf(qp[iq].y, v.y, a);
                a = fmaf(qp[iq].z, v.z, a);
                float d2 = __fadd_rn(__fadd_rn(qp[iq].w, v.w), -__fmul_rn(2.f, a));
                int jj = j;
                if (bad || j == qid[iq] || !qok[iq]) { d2 = inf_f(); jj = 0x7fffffff; }
                unsigned m = __ballot_sync(FULLM, d2 <= kth[iq]);
                if (m) kth[iq] = warp_hits(m, d2, jj, lane, kd[iq], ki[iq]);
            }
        }
    }
#pragma unroll
    for (int iq = 0; iq < QPW; ++iq)
        if (qok[iq] && lane < KNN_K) out_idx[qid[iq] * KNN_K + lane] = ki[iq];
}

// ---------------- 7) epilogue ----------------
__global__ void k_final(const float* __restrict__ tptr, float* __restrict__ out) {
    const int NK = N_NODES * KNN_K;
    int e = blockIdx.x * blockDim.x + threadIdx.x;
    if (e >= NK) return;
    int i = e / KNN_K;
    int src = g_idx_emb[e];
    float s = 0.f;
#pragma unroll
    for (int d = 0; d < D_OUT; ++d) {
        float df = g_embn[src * D_OUT + d] - g_embn[i * D_OUT + d];
        s = fmaf(df, df, s);
    }
    float dist = sqrtf(s);
    float p = expf(-tptr[0] * dist);
    float fi = (float)i;
    float fs = (float)src;

    out[e] = p;
    out[NK + e] = p;
    out[2 * NK + e] = fi;
    out[3 * NK + e] = fs;
    out[4 * NK + e] = fi;
    out[5 * NK + e] = fs;
    out[6 * NK + e] = (float)g_idx_pos[e];
    out[7 * NK + e] = fi;
    out[8 * NK + e] = fi;
}

// ---------------- launch ----------------
extern "C" void kernel_launch(void* const* d_in, const int* in_sizes, int n_in,
                              void* d_out, int out_size) {
    const float* x     = (const float*)d_in[0];
    const float* pos   = (const float*)d_in[1];
    const float* noise = (const float*)d_in[2];
    const float* W     = (const float*)d_in[3];
    const float* b     = (const float*)d_in[4];
    const float* gamma = (const float*)d_in[5];
    const float* beta  = (const float*)d_in[6];
    const float* t     = (const float*)d_in[7];
    float* out = (float*)d_out;

    int nd = N_NODES * D_OUT;
    k_linear<<<(nd + 255) / 256, 256>>>(x, W, b);
    k_stats<<<D_OUT, 256>>>();
    k_emb<<<(nd + 255) / 256, 256>>>(noise, gamma, beta);
    k_sqn<<<(N_NODES + 255) / 256, 256>>>(pos);

    int* d_idx_emb; cudaGetSymbolAddress((void**)&d_idx_emb, g_idx_emb);
    int* d_idx_pos; cudaGetSymbolAddress((void**)&d_idx_pos, g_idx_pos);
    float* d_emb;   cudaGetSymbolAddress((void**)&d_emb, g_emb);
    float* d_sqe;   cudaGetSymbolAddress((void**)&d_sqe, g_sqe);
    float4* d_pos4; cudaGetSymbolAddress((void**)&d_pos4, g_pos4);

    const int nblk = (N_NODES + QPB - 1) / QPB;   // 313
    k_knn_emb<<<nblk, KNN_TPB>>>(d_emb, d_sqe, d_idx_emb);
    k_knn_pos<<<nblk, KNN_TPB>>>(d_pos4, d_idx_pos);

    const int NK = N_NODES * KNN_K;
    k_final<<<(NK + 255) / 256, 256>>>(t, out);
    (void)in_sizes; (void)n_in; (void)out_size;
}

// round 7
// speedup vs baseline: 6.6366x; 6.6366x over previous
#include <cuda_runtime.h>
#include <math.h>

#define N_NODES 10000
#define C_IN 128
#define D_OUT 20
#define KNN_K 16
#define FULLM 0xffffffffu

#define KNN_TPB 256                // threads per knn block
#define WARPS_PB (KNN_TPB / 32)    // 8 warps
#define QPW 2                      // queries per warp (kept small: no spills)
#define QPB (WARPS_PB * QPW)       // 16 queries per block
#define TC 512                     // candidate tile
#define EPAD 22                    // emb smem row stride -> conflict-free float2

// ---------------- scratch (static device globals; no allocs) ----------------
__device__ float g_h[N_NODES * D_OUT];
__device__ float g_emb[N_NODES * D_OUT];
__device__ float g_embn[N_NODES * D_OUT];
__device__ float g_sqe[N_NODES];
__device__ float4 g_pos4[N_NODES];         // {x, y, z, sq}
__device__ float g_mu[D_OUT];
__device__ float g_rinv[D_OUT];
__device__ int   g_idx_emb[N_NODES * KNN_K];
__device__ int   g_idx_pos[N_NODES * KNN_K];

__device__ __forceinline__ float inf_f() { return __int_as_float(0x7f800000); }

// ---------------- 1) linear: h = x @ W + b ----------------
__global__ void k_linear(const float* __restrict__ x, const float* __restrict__ W,
                         const float* __restrict__ b) {
    int t = blockIdx.x * blockDim.x + threadIdx.x;
    if (t >= N_NODES * D_OUT) return;
    int i = t / D_OUT;
    int d = t % D_OUT;
    const float* xr = x + (size_t)i * C_IN;
    float acc = 0.f;
#pragma unroll 8
    for (int c = 0; c < C_IN; ++c) acc = fmaf(xr[c], W[c * D_OUT + d], acc);
    g_h[t] = acc + b[d];
}

// ---------------- 2) batchnorm stats (deterministic) ----------------
__global__ void k_stats() {
    __shared__ float ss[256];
    __shared__ float sq[256];
    int d = blockIdx.x;
    int tid = threadIdx.x;
    float s = 0.f, q = 0.f;
    for (int i = tid; i < N_NODES; i += 256) {
        float v = g_h[i * D_OUT + d];
        s += v;
        q = fmaf(v, v, q);
    }
    ss[tid] = s; sq[tid] = q;
    __syncthreads();
    for (int o = 128; o > 0; o >>= 1) {
        if (tid < o) { ss[tid] += ss[tid + o]; sq[tid] += sq[tid + o]; }
        __syncthreads();
    }
    if (tid == 0) {
        float mu = ss[0] / (float)N_NODES;
        float var = sq[0] / (float)N_NODES - mu * mu;
        g_mu[d] = mu;
        g_rinv[d] = 1.f / sqrtf(var + 1e-5f);
    }
}

// ---------------- 3) emb = relu(bn(h)); embn = emb + noise*1e-4 ----------------
__global__ void k_emb(const float* __restrict__ noise, const float* __restrict__ gamma,
                      const float* __restrict__ beta) {
    int t = blockIdx.x * blockDim.x + threadIdx.x;
    if (t >= N_NODES * D_OUT) return;
    int d = t % D_OUT;
    float e = (g_h[t] - g_mu[d]) * g_rinv[d] * gamma[d] + beta[d];
    e = fmaxf(e, 0.f);
    g_emb[t] = e;
    g_embn[t] = e + noise[t] * 1e-4f;
}

// ---------------- 4) row squared norms; build padded pos4 ----------------
// pos squared-norm mimics jnp.sum(pos*pos, axis=1): separately-rounded squares,
// left-to-right reduction, NO fma contraction (bit-match with reference).
__global__ void k_sqn(const float* __restrict__ pos) {
    int i = blockIdx.x * blockDim.x + threadIdx.x;
    if (i >= N_NODES) return;
    float s = 0.f;
#pragma unroll
    for (int d = 0; d < D_OUT; ++d) {
        float v = g_emb[i * D_OUT + d];
        s = fmaf(v, v, s);
    }
    g_sqe[i] = s;
    float p0 = pos[i * 3 + 0], p1 = pos[i * 3 + 1], p2 = pos[i * 3 + 2];
    float s0 = __fmul_rn(p0, p0);
    float s1 = __fmul_rn(p1, p1);
    float s2 = __fmul_rn(p2, p2);
    float psq = __fadd_rn(__fadd_rn(s0, s1), s2);
    g_pos4[i] = make_float4(p0, p1, p2, psq);
}

// ---------------- warp-distributed top-k ----------------
// lane r holds the r-th smallest (d2, idx); lanes >=16 overflow. All control
// flow warp-uniform. Exactness: the main loop pre-filters with the exact
// lexicographic test vs the current kth; warp_hits rechecks against the
// updated kth, so selection is insert-order independent.
__device__ __forceinline__ bool lt_pair(float d2a, int ia, float d2b, int ib) {
    return (d2a < d2b) || (d2a == d2b && ia < ib);
}

// Processes all flagged lanes; updates kd/ki and the cached kth pair.
__device__ __forceinline__ void warp_hits(unsigned mask, float d2, int jj, int lane,
                                          float& kd, int& ki, float& kth_d, int& kth_i) {
    while (mask) {
        int src = __ffs(mask) - 1;
        mask &= mask - 1;
        float dn = __shfl_sync(FULLM, d2, src);
        int   in = __shfl_sync(FULLM, jj, src);
        if (lt_pair(dn, in, kth_d, kth_i)) {
            bool p = lt_pair(dn, in, kd, ki);
            unsigned pm = __ballot_sync(FULLM, p);
            int pos = __ffs(pm) - 1;
            float kdu = __shfl_up_sync(FULLM, kd, 1);
            int   kiu = __shfl_up_sync(FULLM, ki, 1);
            if (p) {
                kd = (lane == pos) ? dn : kdu;
                ki = (lane == pos) ? in : kiu;
            }
            kth_d = __shfl_sync(FULLM, kd, 15);
            kth_i = __shfl_sync(FULLM, ki, 15);
        }
    }
}

// ---------------- 5a) emb knn: warp handles QPW queries, 2 cands/lane ----------------
__global__ void __launch_bounds__(KNN_TPB) k_knn_emb(const float* __restrict__ feat,
                                                     const float* __restrict__ sqn,
                                                     int* __restrict__ out_idx) {
    __shared__ float s_feat[TC * EPAD];
    __shared__ float s_sq[TC];
    const int lane = threadIdx.x & 31;
    const int wid = threadIdx.x >> 5;
    const int qbase = blockIdx.x * QPB + wid * QPW;   // 625*16 == 10000: always valid

    float qv[QPW][D_OUT];
    float qsq[QPW];
#pragma unroll
    for (int iq = 0; iq < QPW; ++iq) {
        int q = qbase + iq;
        qsq[iq] = sqn[q];
#pragma unroll
        for (int d = 0; d < D_OUT; ++d) qv[iq][d] = feat[(size_t)q * D_OUT + d];
    }

    float kd[QPW]; int ki[QPW]; float kth_d[QPW]; int kth_i[QPW];
#pragma unroll
    for (int iq = 0; iq < QPW; ++iq) {
        kd[iq] = inf_f(); ki[iq] = 0x7fffffff;
        kth_d[iq] = inf_f(); kth_i[iq] = 0x7fffffff;
    }

    for (int base = 0; base < N_NODES; base += TC) {
        const int cnt = min(TC, N_NODES - base);
        __syncthreads();
        for (int idx = threadIdx.x; idx < cnt * D_OUT; idx += KNN_TPB) {
            int c = idx / D_OUT, d = idx - c * D_OUT;
            s_feat[c * EPAD + d] = feat[(size_t)(base + c) * D_OUT + d];
        }
        for (int idx = threadIdx.x; idx < cnt; idx += KNN_TPB)
            s_sq[idx] = sqn[base + idx];
        __syncthreads();

        for (int c0 = 0; c0 < cnt; c0 += 64) {
            const int ca = c0 + lane;
            const int cb = ca + 32;
            const bool bada = (ca >= cnt);
            const bool badb = (cb >= cnt);
            const int csa = bada ? 0 : ca;
            const int csb = badb ? 0 : cb;
            const int ja = base + csa;
            const int jb = base + csb;
            const float ssqa = s_sq[csa];
            const float ssqb = s_sq[csb];
            const float2* ra = (const float2*)&s_feat[csa * EPAD];
            const float2* rb = (const float2*)&s_feat[csb * EPAD];

            float a0[QPW], a1[QPW];
#pragma unroll
            for (int iq = 0; iq < QPW; ++iq) { a0[iq] = 0.f; a1[iq] = 0.f; }
#pragma unroll
            for (int kk = 0; kk < D_OUT / 2; ++kk) {
                float2 va = ra[kk];
                float2 vb = rb[kk];
#pragma unroll
                for (int iq = 0; iq < QPW; ++iq) {
                    a0[iq] = fmaf(qv[iq][2 * kk], va.x, a0[iq]);
                    a0[iq] = fmaf(qv[iq][2 * kk + 1], va.y, a0[iq]);
                    a1[iq] = fmaf(qv[iq][2 * kk], vb.x, a1[iq]);
                    a1[iq] = fmaf(qv[iq][2 * kk + 1], vb.y, a1[iq]);
                }
            }
#pragma unroll
            for (int iq = 0; iq < QPW; ++iq) {
                const int q = qbase + iq;
                float d2a = fmaf(-2.f, a0[iq], qsq[iq] + ssqa);
                float d2b = fmaf(-2.f, a1[iq], qsq[iq] + ssqb);
                int jja = ja, jjb = jb;
                if (bada || ja == q) { d2a = inf_f(); jja = 0x7fffffff; }
                if (badb || jb == q) { d2b = inf_f(); jjb = 0x7fffffff; }
                unsigned m0 = __ballot_sync(FULLM, lt_pair(d2a, jja, kth_d[iq], kth_i[iq]));
                unsigned m1 = __ballot_sync(FULLM, lt_pair(d2b, jjb, kth_d[iq], kth_i[iq]));
                if (m0) warp_hits(m0, d2a, jja, lane, kd[iq], ki[iq], kth_d[iq], kth_i[iq]);
                if (m1) warp_hits(m1, d2b, jjb, lane, kd[iq], ki[iq], kth_d[iq], kth_i[iq]);
            }
        }
    }
#pragma unroll
    for (int iq = 0; iq < QPW; ++iq)
        if (lane < KNN_K) out_idx[(qbase + iq) * KNN_K + lane] = ki[iq];
}

// ---------------- 5b) pos knn: warp handles QPW queries, 2 cands/lane ----------------
__global__ void __launch_bounds__(KNN_TPB) k_knn_pos(const float4* __restrict__ p4,
                                                     int* __restrict__ out_idx) {
    __shared__ float4 s_p[TC];
    const int lane = threadIdx.x & 31;
    const int wid = threadIdx.x >> 5;
    const int qbase = blockIdx.x * QPB + wid * QPW;

    float4 qp[QPW];
#pragma unroll
    for (int iq = 0; iq < QPW; ++iq) qp[iq] = p4[qbase + iq];

    float kd[QPW]; int ki[QPW]; float kth_d[QPW]; int kth_i[QPW];
#pragma unroll
    for (int iq = 0; iq < QPW; ++iq) {
        kd[iq] = inf_f(); ki[iq] = 0x7fffffff;
        kth_d[iq] = inf_f(); kth_i[iq] = 0x7fffffff;
    }

    for (int base = 0; base < N_NODES; base += TC) {
        const int cnt = min(TC, N_NODES - base);
        __syncthreads();
        for (int idx = threadIdx.x; idx < cnt; idx += KNN_TPB)
            s_p[idx] = p4[base + idx];
        __syncthreads();

        for (int c0 = 0; c0 < cnt; c0 += 64) {
            const int ca = c0 + lane;
            const int cb = ca + 32;
            const bool bada = (ca >= cnt);
            const bool badb = (cb >= cnt);
            const int csa = bada ? 0 : ca;
            const int csb = badb ? 0 : cb;
            const int ja = base + csa;
            const int jb = base + csb;
            const float4 va = s_p[csa];
            const float4 vb = s_p[csb];
#pragma unroll
            for (int iq = 0; iq < QPW; ++iq) {
                const int q = qbase + iq;
                // dot as ascending fma chain; d2 = fl(fl(sqi+sqj) - fl(2*dot))
                float a = fmaf(qp[iq].x, va.x, 0.f);
                a = fmaf(qp[iq].y, va.y, a);
                a = fmaf(qp[iq].z, va.z, a);
                float b = fmaf(qp[iq].x, vb.x, 0.f);
                b = fmaf(qp[iq].y, vb.y, b);
                b = fmaf(qp[iq].z, vb.z, b);
                float d2a = __fadd_rn(__fadd_rn(qp[iq].w, va.w), -__fmul_rn(2.f, a));
                float d2b = __fadd_rn(__fadd_rn(qp[iq].w, vb.w), -__fmul_rn(2.f, b));
                int jja = ja, jjb = jb;
                if (bada || ja == q) { d2a = inf_f(); jja = 0x7fffffff; }
                if (badb || jb == q) { d2b = inf_f(); jjb = 0x7fffffff; }
                unsigned m0 = __ballot_sync(FULLM, lt_pair(d2a, jja, kth_d[iq], kth_i[iq]));
                unsigned m1 = __ballot_sync(FULLM, lt_pair(d2b, jjb, kth_d[iq], kth_i[iq]));
                if (m0) warp_hits(m0, d2a, jja, lane, kd[iq], ki[iq], kth_d[iq], kth_i[iq]);
                if (m1) warp_hits(m1, d2b, jjb, lane, kd[iq], ki[iq], kth_d[iq], kth_i[iq]);
            }
        }
    }
#pragma unroll
    for (int iq = 0; iq < QPW; ++iq)
        if (lane < KNN_K) out_idx[(qbase + iq) * KNN_K + lane] = ki[iq];
}

// ---------------- 7) epilogue ----------------
__global__ void k_final(const float* __restrict__ tptr, float* __restrict__ out) {
    const int NK = N_NODES * KNN_K;
    int e = blockIdx.x * blockDim.x + threadIdx.x;
    if (e >= NK) return;
    int i = e / KNN_K;
    int src = g_idx_emb[e];
    float s = 0.f;
#pragma unroll
    for (int d = 0; d < D_OUT; ++d) {
        float df = g_embn[src * D_OUT + d] - g_embn[i * D_OUT + d];
        s = fmaf(df, df, s);
    }
    float dist = sqrtf(s);
    float p = expf(-tptr[0] * dist);
    float fi = (float)i;
    float fs = (float)src;

    out[e] = p;
    out[NK + e] = p;
    out[2 * NK + e] = fi;
    out[3 * NK + e] = fs;
    out[4 * NK + e] = fi;
    out[5 * NK + e] = fs;
    out[6 * NK + e] = (float)g_idx_pos[e];
    out[7 * NK + e] = fi;
    out[8 * NK + e] = fi;
}

// ---------------- launch ----------------
extern "C" void kernel_launch(void* const* d_in, const int* in_sizes, int n_in,
                              void* d_out, int out_size) {
    const float* x     = (const float*)d_in[0];
    const float* pos   = (const float*)d_in[1];
    const float* noise = (const float*)d_in[2];
    const float* W     = (const float*)d_in[3];
    const float* b     = (const float*)d_in[4];
    const float* gamma = (const float*)d_in[5];
    const float* beta  = (const float*)d_in[6];
    const float* t     = (const float*)d_in[7];
    float* out = (float*)d_out;

    int nd = N_NODES * D_OUT;
    k_linear<<<(nd + 255) / 256, 256>>>(x, W, b);
    k_stats<<<D_OUT, 256>>>();
    k_emb<<<(nd + 255) / 256, 256>>>(noise, gamma, beta);
    k_sqn<<<(N_NODES + 255) / 256, 256>>>(pos);

    int* d_idx_emb; cudaGetSymbolAddress((void**)&d_idx_emb, g_idx_emb);
    int* d_idx_pos; cudaGetSymbolAddress((void**)&d_idx_pos, g_idx_pos);
    float* d_emb;   cudaGetSymbolAddress((void**)&d_emb, g_emb);
    float* d_sqe;   cudaGetSymbolAddress((void**)&d_sqe, g_sqe);
    float4* d_pos4; cudaGetSymbolAddress((void**)&d_pos4, g_pos4);

    const int nblk = N_NODES / QPB;   // 625
    k_knn_emb<<<nblk, KNN_TPB>>>(d_emb, d_sqe, d_idx_emb);
    k_knn_pos<<<nblk, KNN_TPB>>>(d_pos4, d_idx_pos);

    const int NK = N_NODES * KNN_K;
    k_final<<<(NK + 255) / 256, 256>>>(t, out);
    (void)in_sizes; (void)n_in; (void)out_size;
}